// round 4
// baseline (speedup 1.0000x reference)
#include <cuda_runtime.h>
#include <math.h>

#define F    1433
#define FP   1536          // padded feature dim (24 * 64)
#define BB   64            // batch
#define KNB  8             // neighbors
#define NC   7             // classes
#define NBF  91712.0f      // BB * F
#define EPS  1e-5f

// ---------------- device scratch ----------------
__device__ float g_xs  [BB*FP];
__device__ float g_ys  [BB*FP];
__device__ float g_den [BB*FP];
__device__ float g_rden[BB*FP];
__device__ float g_w   [BB*FP];
__device__ float g_s1  [BB*FP];
__device__ float g_adj [FP*FP];     // adj_tot (padded)
__device__ float g_hn  [FP*128];    // h1n transposed: [g][n], n = b*2+c
__device__ float g_z   [FP*128];    // layer-2 pre-conv: [f][n]
__device__ float g_acc [8];         // sums: s1, s1^2, v0, v1, v0^2, v1^2

typedef unsigned long long u64t;

__device__ __forceinline__ float fsqrt_a(float x){ float r; asm("sqrt.approx.f32 %0,%1;" : "=f"(r) : "f"(x)); return r; }
__device__ __forceinline__ float frcp_a (float x){ float r; asm("rcp.approx.f32 %0,%1;"  : "=f"(r) : "f"(x)); return r; }

__device__ __forceinline__ u64t pk(float a, float b){ u64t r; asm("mov.b64 %0,{%1,%2};" : "=l"(r) : "f"(a), "f"(b)); return r; }
__device__ __forceinline__ void upk(u64t v, float &a, float &b){ asm("mov.b64 {%0,%1},%2;" : "=f"(a), "=f"(b) : "l"(v)); }
__device__ __forceinline__ u64t fma2(u64t a, u64t b, u64t c){ u64t r; asm("fma.rn.f32x2 %0,%1,%2,%3;" : "=l"(r) : "l"(a), "l"(b), "l"(c)); return r; }
__device__ __forceinline__ u64t mul2(u64t a, u64t b){ u64t r; asm("mul.rn.f32x2 %0,%1,%2;" : "=l"(r) : "l"(a), "l"(b)); return r; }

// ---------------- k_init: xs, ys, den=0, z=0, acc=0 ------------------------
__global__ void k_init(const float* __restrict__ x, const float* __restrict__ nb){
    int idx = blockIdx.x * 256 + threadIdx.x;        // covers FP*128
    if (idx < 8) g_acc[idx] = 0.f;
    g_z[idx] = 0.f;
    if (idx < BB*FP){
        int b = idx / FP, g = idx - b*FP;
        float xv = 0.f, yv = 0.f;
        if (g < F){
            xv = x[b*F + g];
            const float* p = nb + (size_t)b*KNB*F + g;
            #pragma unroll
            for (int k = 0; k < KNB; k++) yv += p[k*F];
        }
        g_xs[idx] = xv; g_ys[idx] = yv; g_den[idx] = 0.f;
    }
}

// ---------------- k_den: den[b,g] += sum_f sqrt(xs_f*ys_g + xs_g*ys_f) -----
// Block tile: 64 f (tx: 8 groups x 8) x 128 g (ty: 32 groups x 4). Grid 24x12.
__global__ void __launch_bounds__(256) k_den(){
    __shared__ float shf[8][2][64];
    __shared__ float shg[8][2][128];
    int fb = blockIdx.x * 64, gb = blockIdx.y * 128;
    int tid = threadIdx.x, tx = tid & 7, ty = tid >> 3;

    for (int bs = 0; bs < BB; bs += 8){
        __syncthreads();
        #pragma unroll
        for (int v = tid; v < 768; v += 256){
            if (v < 256){
                int bl = v >> 5, r = v & 31, a = r >> 4, e4 = r & 15;
                ((float4*)&shf[bl][a][0])[e4] =
                    *(const float4*)&((a ? g_ys : g_xs)[(bs+bl)*FP + fb + e4*4]);
            } else {
                int v2 = v - 256;
                int bl = v2 >> 6, r = v2 & 63, a = r >> 5, e4 = r & 31;
                ((float4*)&shg[bl][a][0])[e4] =
                    *(const float4*)&((a ? g_ys : g_xs)[(bs+bl)*FP + gb + e4*4]);
            }
        }
        __syncthreads();
        #pragma unroll 1
        for (int bl = 0; bl < 8; bl++){
            float4 xgv = ((float4*)&shg[bl][0][0])[ty];
            float4 ygv = ((float4*)&shg[bl][1][0])[ty];
            u64t xg2[2] = { pk(xgv.x, xgv.y), pk(xgv.z, xgv.w) };
            u64t yg2[2] = { pk(ygv.x, ygv.y), pk(ygv.z, ygv.w) };
            float xf[8], yf[8];
            *(float4*)&xf[0] = ((float4*)&shf[bl][0][0])[tx*2];
            *(float4*)&xf[4] = ((float4*)&shf[bl][0][0])[tx*2+1];
            *(float4*)&yf[0] = ((float4*)&shf[bl][1][0])[tx*2];
            *(float4*)&yf[4] = ((float4*)&shf[bl][1][0])[tx*2+1];
            float cs[4] = {0,0,0,0};
            #pragma unroll
            for (int i = 0; i < 8; i++){
                u64t xf2 = pk(xf[i], xf[i]), yf2 = pk(yf[i], yf[i]);
                #pragma unroll
                for (int j2 = 0; j2 < 2; j2++){
                    float a0, a1;
                    upk(fma2(xg2[j2], yf2, mul2(yg2[j2], xf2)), a0, a1);
                    cs[2*j2]   += fsqrt_a(a0);
                    cs[2*j2+1] += fsqrt_a(a1);
                }
            }
            #pragma unroll
            for (int j = 0; j < 4; j++){
                float v = cs[j];
                v += __shfl_xor_sync(0xffffffffu, v, 1);
                v += __shfl_xor_sync(0xffffffffu, v, 2);
                v += __shfl_xor_sync(0xffffffffu, v, 4);
                cs[j] = v;
            }
            if (tx == 0){
                #pragma unroll
                for (int j = 0; j < 4; j++)
                    atomicAdd(&g_den[(bs+bl)*FP + gb + ty*4 + j], cs[j]);
            }
        }
    }
}

// ---------------- k_rw: rden, w = xs/den, s1 init = xs ----------------------
__global__ void k_rw(){
    int idx = blockIdx.x * 256 + threadIdx.x;
    if (idx >= BB*FP) return;
    int g = idx % FP;
    float d = g_den[idx];
    float r = (g < F && d > 0.f) ? frcp_a(d) : 0.f;
    g_rden[idx] = r;
    g_w[idx]    = g_xs[idx] * r;
    g_s1[idx]   = (g < F) ? g_xs[idx] : 0.f;
}

// ---------------- k_main: adj tile (owned) + s1 ------------------------------
// Block tile: 128 f (ty: 32 groups x 4) x 64 g (tx: 8 groups x 8). Grid 12x24.
__global__ void __launch_bounds__(256) k_main(const float* __restrict__ adjbuf){
    __shared__ float shf[8][2][128];
    __shared__ float shg[8][4][64];
    int fb = blockIdx.x * 128, gb = blockIdx.y * 64;
    int tid = threadIdx.x, tx = tid & 7, ty = tid >> 3;

    u64t accA[4][4];
    #pragma unroll
    for (int i = 0; i < 4; i++)
        #pragma unroll
        for (int j = 0; j < 4; j++) accA[i][j] = 0ULL;

    for (int bs = 0; bs < BB; bs += 8){
        __syncthreads();
        #pragma unroll
        for (int v = tid; v < 1024; v += 256){
            if (v < 512){
                int bl = v >> 6, r = v & 63, a = r >> 5, e4 = r & 31;
                ((float4*)&shf[bl][a][0])[e4] =
                    *(const float4*)&((a ? g_ys : g_xs)[(bs+bl)*FP + fb + e4*4]);
            } else {
                int v2 = v - 512;
                int bl = v2 >> 6, r = v2 & 63, a = r >> 4, e4 = r & 15;
                const float* src = (a == 0) ? g_xs : (a == 1) ? g_ys : (a == 2) ? g_w : g_rden;
                ((float4*)&shg[bl][a][0])[e4] =
                    *(const float4*)&(src[(bs+bl)*FP + gb + e4*4]);
            }
        }
        __syncthreads();
        #pragma unroll 1
        for (int bl = 0; bl < 8; bl++){
            float xf[4], yf[4];
            *(float4*)&xf[0] = ((float4*)&shf[bl][0][0])[ty];
            *(float4*)&yf[0] = ((float4*)&shf[bl][1][0])[ty];
            u64t xg2[4], yg2[4], wg2[4], rg2[4];
            {
                float4 q0 = ((float4*)&shg[bl][0][0])[tx*2], q1 = ((float4*)&shg[bl][0][0])[tx*2+1];
                xg2[0]=pk(q0.x,q0.y); xg2[1]=pk(q0.z,q0.w); xg2[2]=pk(q1.x,q1.y); xg2[3]=pk(q1.z,q1.w);
                q0 = ((float4*)&shg[bl][1][0])[tx*2]; q1 = ((float4*)&shg[bl][1][0])[tx*2+1];
                yg2[0]=pk(q0.x,q0.y); yg2[1]=pk(q0.z,q0.w); yg2[2]=pk(q1.x,q1.y); yg2[3]=pk(q1.z,q1.w);
                q0 = ((float4*)&shg[bl][2][0])[tx*2]; q1 = ((float4*)&shg[bl][2][0])[tx*2+1];
                wg2[0]=pk(q0.x,q0.y); wg2[1]=pk(q0.z,q0.w); wg2[2]=pk(q1.x,q1.y); wg2[3]=pk(q1.z,q1.w);
                q0 = ((float4*)&shg[bl][3][0])[tx*2]; q1 = ((float4*)&shg[bl][3][0])[tx*2+1];
                rg2[0]=pk(q0.x,q0.y); rg2[1]=pk(q0.z,q0.w); rg2[2]=pk(q1.x,q1.y); rg2[3]=pk(q1.z,q1.w);
            }
            u64t r1f2[4] = {0ULL,0ULL,0ULL,0ULL};
            #pragma unroll
            for (int i = 0; i < 4; i++){
                u64t xf2 = pk(xf[i], xf[i]), yf2 = pk(yf[i], yf[i]);
                #pragma unroll
                for (int j2 = 0; j2 < 4; j2++){
                    float a0, a1;
                    upk(fma2(xg2[j2], yf2, mul2(yg2[j2], xf2)), a0, a1);
                    u64t t2 = pk(fsqrt_a(a0), fsqrt_a(a1));
                    accA[i][j2] = fma2(t2, rg2[j2], accA[i][j2]);
                    r1f2[i]     = fma2(t2, wg2[j2], r1f2[i]);
                }
            }
            #pragma unroll
            for (int i = 0; i < 4; i++){
                float a0, a1; upk(r1f2[i], a0, a1);
                float v = a0 + a1;
                v += __shfl_xor_sync(0xffffffffu, v, 1);
                v += __shfl_xor_sync(0xffffffffu, v, 2);
                v += __shfl_xor_sync(0xffffffffu, v, 4);
                if (tx == 0)
                    atomicAdd(&g_s1[(bs+bl)*FP + fb + ty*4 + i], v);
            }
        }
    }

    // exclusive tile ownership: plain store with adjbuf + 64*eye folded in
    #pragma unroll
    for (int i = 0; i < 4; i++){
        int f = fb + ty*4 + i;
        int gBase = gb + tx*8;
        float vals[8];
        #pragma unroll
        for (int j2 = 0; j2 < 4; j2++) upk(accA[i][j2], vals[2*j2], vals[2*j2+1]);
        if (f < F){
            #pragma unroll
            for (int j = 0; j < 8; j++){
                int g = gBase + j;
                if (g < F) vals[j] += adjbuf[f*F + g];
                if (g == f) vals[j] += 64.0f;
            }
        }
        *(float4*)&g_adj[f*FP + gBase]     = *(float4*)&vals[0];
        *(float4*)&g_adj[f*FP + gBase + 4] = *(float4*)&vals[4];
    }
}

// ---------------- block reduction helper ------------------------------------
__device__ __forceinline__ float block_sum(float v, float* sred){
    #pragma unroll
    for (int m = 16; m; m >>= 1) v += __shfl_xor_sync(0xffffffffu, v, m);
    int lane = threadIdx.x & 31, w = threadIdx.x >> 5;
    __syncthreads();
    if (lane == 0) sred[w] = v;
    __syncthreads();
    if (w == 0){
        v = (lane < (int)(blockDim.x >> 5)) ? sred[lane] : 0.f;
        #pragma unroll
        for (int m = 16; m; m >>= 1) v += __shfl_xor_sync(0xffffffffu, v, m);
    }
    return v;
}

// ---------------- k_stats1: one-pass sum + sumsq of s1 ----------------------
__global__ void k_stats1(){
    __shared__ float sred[32];
    int idx = blockIdx.x * 1024 + threadIdx.x;       // exactly BB*FP
    float v = g_s1[idx];                              // pads are 0
    float s = block_sum(v, sred);
    if (threadIdx.x == 0) atomicAdd(&g_acc[0], s);
    float q = block_sum(v*v, sred);
    if (threadIdx.x == 0) atomicAdd(&g_acc[1], q);
}

// ---------------- k_hn1: BN1 + softsign, transposed [g][n] ------------------
__global__ void k_hn1(const float* __restrict__ W1, const float* __restrict__ g1,
                      const float* __restrict__ be1){
    int idx = blockIdx.x * 256 + threadIdx.x;
    if (idx >= FP*128) return;
    int g = idx >> 7, n = idx & 127;
    int b = n >> 1, c = n & 1;
    float out = 0.f;
    if (g < F){
        float ms = g_acc[0] * (1.f/NBF);
        float vs = g_acc[1] * (1.f/NBF) - ms*ms;
        float w  = W1[c];
        float A  = g1[c] * w * rsqrtf(w*w*vs + EPS);
        float h  = fmaf(A, g_s1[b*FP+g] - ms, be1[c]);
        out = h * frcp_a(1.f + fabsf(h));
    }
    g_hn[idx] = out;
}

// ---------------- k_gemm: z[f,n] = sum_g adj[f,g]*hn[g,n] -------------------
#define GK 96
#define GT 32
__global__ void __launch_bounds__(256) k_gemm(){
    __shared__ float sa[64][GT+1];
    __shared__ float sb[GT][128];
    int fb = blockIdx.x * 64;
    int g0base = blockIdx.y * GK;
    int tid = threadIdx.x, tx = tid & 15, ty = tid >> 4;
    u64t acc2[4][4];
    #pragma unroll
    for (int i = 0; i < 4; i++)
        #pragma unroll
        for (int j = 0; j < 4; j++) acc2[i][j] = 0ULL;
    for (int kc = 0; kc < GK; kc += GT){
        int g0 = g0base + kc;
        __syncthreads();
        for (int i = tid; i < 64*GT; i += 256){
            int r = i >> 5, c = i & 31;
            sa[r][c] = g_adj[(fb+r)*FP + g0 + c];
        }
        for (int i = tid; i < GT*32; i += 256){
            int r = i >> 5, c = i & 31;
            ((float4*)&sb[r][0])[c] = ((const float4*)(g_hn + (size_t)(g0+r)*128))[c];
        }
        __syncthreads();
        #pragma unroll
        for (int k = 0; k < GT; k++){
            u64t bv[4];
            {
                float4 q0 = ((float4*)&sb[k][0])[tx*2], q1 = ((float4*)&sb[k][0])[tx*2+1];
                bv[0]=pk(q0.x,q0.y); bv[1]=pk(q0.z,q0.w); bv[2]=pk(q1.x,q1.y); bv[3]=pk(q1.z,q1.w);
            }
            #pragma unroll
            for (int i = 0; i < 4; i++){
                float a = sa[ty*4+i][k];
                u64t a2 = pk(a, a);
                #pragma unroll
                for (int j = 0; j < 4; j++) acc2[i][j] = fma2(a2, bv[j], acc2[i][j]);
            }
        }
    }
    #pragma unroll
    for (int i = 0; i < 4; i++){
        float vals[8];
        #pragma unroll
        for (int j = 0; j < 4; j++) upk(acc2[i][j], vals[2*j], vals[2*j+1]);
        #pragma unroll
        for (int j = 0; j < 8; j++)
            atomicAdd(&g_z[(fb+ty*4+i)*128 + tx*8+j], vals[j]);
    }
}

// ---------------- k_stats2: one-pass BN2 sums --------------------------------
__global__ void k_stats2(const float* __restrict__ W2, const float* __restrict__ b2){
    __shared__ float sred[32];
    int idx = blockIdx.x * 1024 + threadIdx.x;
    float v0 = 0.f, v1 = 0.f;
    if (idx < BB*F){
        int f = idx >> 6, b = idx & 63;
        float z0 = g_z[f*128 + 2*b], z1 = g_z[f*128 + 2*b + 1];
        v0 = fmaf(W2[0], z0, fmaf(W2[1], z1, b2[0]));
        v1 = fmaf(W2[2], z0, fmaf(W2[3], z1, b2[1]));
    }
    float s;
    s = block_sum(v0,    sred); if (threadIdx.x == 0) atomicAdd(&g_acc[2], s);
    s = block_sum(v1,    sred); if (threadIdx.x == 0) atomicAdd(&g_acc[3], s);
    s = block_sum(v0*v0, sred); if (threadIdx.x == 0) atomicAdd(&g_acc[4], s);
    s = block_sum(v1*v1, sred); if (threadIdx.x == 0) atomicAdd(&g_acc[5], s);
}

// ---------------- k_final: BN2 + softsign + classifier ----------------------
__global__ void k_final(const float* __restrict__ W2, const float* __restrict__ b2,
                        const float* __restrict__ g2, const float* __restrict__ be2,
                        const float* __restrict__ Wc, const float* __restrict__ bc,
                        float* __restrict__ out){
    __shared__ float red[256];
    int b = blockIdx.x, tid = threadIdx.x;
    float m0 = g_acc[2] * (1.f/NBF), m1 = g_acc[3] * (1.f/NBF);
    float A0 = g2[0] * rsqrtf(g_acc[4]*(1.f/NBF) - m0*m0 + EPS);
    float A1 = g2[1] * rsqrtf(g_acc[5]*(1.f/NBF) - m1*m1 + EPS);
    float w00 = W2[0], w01 = W2[1], w10 = W2[2], w11 = W2[3];
    float bb0 = b2[0], bb1 = b2[1], e0 = be2[0], e1 = be2[1];
    float acc[NC] = {};
    for (int f = tid; f < F; f += 256){
        float z0 = g_z[f*128 + 2*b], z1 = g_z[f*128 + 2*b + 1];
        float h0 = fmaf(w00, z0, fmaf(w01, z1, bb0));
        h0 = fmaf(A0, h0 - m0, e0);
        h0 = h0 * frcp_a(1.f + fabsf(h0));
        float h1 = fmaf(w10, z0, fmaf(w11, z1, bb1));
        h1 = fmaf(A1, h1 - m1, e1);
        h1 = h1 * frcp_a(1.f + fabsf(h1));
        #pragma unroll
        for (int k = 0; k < NC; k++)
            acc[k] += fmaf(h0, Wc[k*(2*F) + f], h1 * Wc[k*(2*F) + F + f]);
    }
    for (int k = 0; k < NC; k++){
        __syncthreads();
        red[tid] = acc[k];
        __syncthreads();
        for (int s = 128; s; s >>= 1){ if (tid < s) red[tid] += red[tid+s]; __syncthreads(); }
        if (tid == 0) out[b*NC + k] = red[0] + bc[k];
    }
}

// ---------------- launch -----------------------------------------------------
extern "C" void kernel_launch(void* const* d_in, const int* in_sizes, int n_in,
                              void* d_out, int out_size){
    const float* x    = (const float*)d_in[0];
    const float* nb   = (const float*)d_in[1];
    const float* adjb = (const float*)d_in[2];
    const float* W1   = (const float*)d_in[3];
    const float* W2   = (const float*)d_in[5];
    const float* b2   = (const float*)d_in[6];
    const float* g1   = (const float*)d_in[7];
    const float* be1  = (const float*)d_in[8];
    const float* g2   = (const float*)d_in[9];
    const float* be2  = (const float*)d_in[10];
    const float* Wc   = (const float*)d_in[11];
    const float* bc   = (const float*)d_in[12];
    float* out = (float*)d_out;

    k_init<<<(FP*128)/256, 256>>>(x, nb);
    k_den<<<dim3(24, 12), 256>>>();
    k_rw<<<(BB*FP)/256, 256>>>();
    k_main<<<dim3(12, 24), 256>>>(adjb);
    k_stats1<<<(BB*FP)/1024, 1024>>>();
    k_hn1<<<(FP*128)/256, 256>>>(W1, g1, be1);
    k_gemm<<<dim3(24, FP/GK), 256>>>();
    k_stats2<<<(BB*F + 1023)/1024, 1024>>>(W2, b2);
    k_final<<<BB, 256>>>(W2, b2, g2, be2, Wc, bc, out);
}

// round 5
// speedup vs baseline: 1.0037x; 1.0037x over previous
#include <cuda_runtime.h>
#include <math.h>

#define F    1433
#define FP   1536          // padded feature dim (24 * 64)
#define BB   64            // batch
#define KNB  8             // neighbors
#define NC   7             // classes
#define NBF  91712.0f      // BB * F
#define EPS  1e-5f

// ---------------- device scratch ----------------
__device__ float g_xs  [BB*FP];
__device__ float g_ys  [BB*FP];
__device__ float g_den [BB*FP];
__device__ float g_rden[BB*FP];
__device__ float g_w   [BB*FP];
__device__ float g_s1  [BB*FP];
__device__ float g_adj [FP*FP];     // adj_tot (padded)
__device__ float g_hn  [FP*128];    // h1n transposed: [g][n], n = b*2+c
__device__ float g_z   [FP*128];    // layer-2 pre-conv: [f][n]
__device__ float g_acc [8];         // sums: s1, s1^2, v0, v1, v0^2, v1^2

typedef unsigned long long u64t;

__device__ __forceinline__ float fsqrt_a(float x){ float r; asm("sqrt.approx.f32 %0,%1;" : "=f"(r) : "f"(x)); return r; }
__device__ __forceinline__ float frcp_a (float x){ float r; asm("rcp.approx.f32 %0,%1;"  : "=f"(r) : "f"(x)); return r; }

__device__ __forceinline__ u64t pk(float a, float b){ u64t r; asm("mov.b64 %0,{%1,%2};" : "=l"(r) : "f"(a), "f"(b)); return r; }
__device__ __forceinline__ void upk(u64t v, float &a, float &b){ asm("mov.b64 {%0,%1},%2;" : "=f"(a), "=f"(b) : "l"(v)); }
__device__ __forceinline__ u64t fma2(u64t a, u64t b, u64t c){ u64t r; asm("fma.rn.f32x2 %0,%1,%2,%3;" : "=l"(r) : "l"(a), "l"(b), "l"(c)); return r; }
__device__ __forceinline__ u64t mul2(u64t a, u64t b){ u64t r; asm("mul.rn.f32x2 %0,%1,%2;" : "=l"(r) : "l"(a), "l"(b)); return r; }

// ---------------- k_init: xs, ys, den=0, z=0, acc=0 ------------------------
__global__ void k_init(const float* __restrict__ x, const float* __restrict__ nb){
    int idx = blockIdx.x * 256 + threadIdx.x;        // covers FP*128
    if (idx < 8) g_acc[idx] = 0.f;
    g_z[idx] = 0.f;
    if (idx < BB*FP){
        int b = idx / FP, g = idx - b*FP;
        float xv = 0.f, yv = 0.f;
        if (g < F){
            xv = x[b*F + g];
            const float* p = nb + (size_t)b*KNB*F + g;
            #pragma unroll
            for (int k = 0; k < KNB; k++) yv += p[k*F];
        }
        g_xs[idx] = xv; g_ys[idx] = yv; g_den[idx] = 0.f;
    }
}

// ---------------- k_den: den[b,g] += sum_f sqrt(xs_f*ys_g + xs_g*ys_f) -----
// Block tile: 64 f (tx: 8 groups x 8) x 128 g (ty: 32 groups x 4). Grid 24x12.
__global__ void __launch_bounds__(256) k_den(){
    __shared__ float shf[8][2][64];
    __shared__ float shg[8][2][128];
    int fb = blockIdx.x * 64, gb = blockIdx.y * 128;
    int tid = threadIdx.x, tx = tid & 7, ty = tid >> 3;

    for (int bs = 0; bs < BB; bs += 8){
        __syncthreads();
        #pragma unroll
        for (int v = tid; v < 768; v += 256){
            if (v < 256){
                int bl = v >> 5, r = v & 31, a = r >> 4, e4 = r & 15;
                ((float4*)&shf[bl][a][0])[e4] =
                    *(const float4*)&((a ? g_ys : g_xs)[(bs+bl)*FP + fb + e4*4]);
            } else {
                int v2 = v - 256;
                int bl = v2 >> 6, r = v2 & 63, a = r >> 5, e4 = r & 31;
                ((float4*)&shg[bl][a][0])[e4] =
                    *(const float4*)&((a ? g_ys : g_xs)[(bs+bl)*FP + gb + e4*4]);
            }
        }
        __syncthreads();
        #pragma unroll 1
        for (int bl = 0; bl < 8; bl++){
            float4 xgv = ((float4*)&shg[bl][0][0])[ty];
            float4 ygv = ((float4*)&shg[bl][1][0])[ty];
            u64t xg2[2] = { pk(xgv.x, xgv.y), pk(xgv.z, xgv.w) };
            u64t yg2[2] = { pk(ygv.x, ygv.y), pk(ygv.z, ygv.w) };
            float xf[8], yf[8];
            *(float4*)&xf[0] = ((float4*)&shf[bl][0][0])[tx*2];
            *(float4*)&xf[4] = ((float4*)&shf[bl][0][0])[tx*2+1];
            *(float4*)&yf[0] = ((float4*)&shf[bl][1][0])[tx*2];
            *(float4*)&yf[4] = ((float4*)&shf[bl][1][0])[tx*2+1];
            float cs[4] = {0,0,0,0};
            #pragma unroll
            for (int i = 0; i < 8; i++){
                u64t xf2 = pk(xf[i], xf[i]), yf2 = pk(yf[i], yf[i]);
                #pragma unroll
                for (int j2 = 0; j2 < 2; j2++){
                    float a0, a1;
                    upk(fma2(xg2[j2], yf2, mul2(yg2[j2], xf2)), a0, a1);
                    cs[2*j2]   += fsqrt_a(a0);
                    cs[2*j2+1] += fsqrt_a(a1);
                }
            }
            #pragma unroll
            for (int j = 0; j < 4; j++){
                float v = cs[j];
                v += __shfl_xor_sync(0xffffffffu, v, 1);
                v += __shfl_xor_sync(0xffffffffu, v, 2);
                v += __shfl_xor_sync(0xffffffffu, v, 4);
                cs[j] = v;
            }
            if (tx == 0){
                #pragma unroll
                for (int j = 0; j < 4; j++)
                    atomicAdd(&g_den[(bs+bl)*FP + gb + ty*4 + j], cs[j]);
            }
        }
    }
}

// ---------------- k_rw: rden, w = xs/den, s1 init = xs ----------------------
__global__ void k_rw(){
    int idx = blockIdx.x * 256 + threadIdx.x;
    if (idx >= BB*FP) return;
    int g = idx % FP;
    float d = g_den[idx];
    float r = (g < F && d > 0.f) ? frcp_a(d) : 0.f;
    g_rden[idx] = r;
    g_w[idx]    = g_xs[idx] * r;
    g_s1[idx]   = (g < F) ? g_xs[idx] : 0.f;
}

// ---------------- k_main: adj tile (owned) + s1 ------------------------------
// Block tile: 128 f (ty: 32 groups x 4) x 64 g (tx: 8 groups x 8). Grid 12x24.
__global__ void __launch_bounds__(256) k_main(const float* __restrict__ adjbuf){
    __shared__ float shf[8][2][128];
    __shared__ float shg[8][4][64];
    int fb = blockIdx.x * 128, gb = blockIdx.y * 64;
    int tid = threadIdx.x, tx = tid & 7, ty = tid >> 3;

    u64t accA[4][4];
    #pragma unroll
    for (int i = 0; i < 4; i++)
        #pragma unroll
        for (int j = 0; j < 4; j++) accA[i][j] = 0ULL;

    for (int bs = 0; bs < BB; bs += 8){
        __syncthreads();
        #pragma unroll
        for (int v = tid; v < 1024; v += 256){
            if (v < 512){
                int bl = v >> 6, r = v & 63, a = r >> 5, e4 = r & 31;
                ((float4*)&shf[bl][a][0])[e4] =
                    *(const float4*)&((a ? g_ys : g_xs)[(bs+bl)*FP + fb + e4*4]);
            } else {
                int v2 = v - 512;
                int bl = v2 >> 6, r = v2 & 63, a = r >> 4, e4 = r & 15;
                const float* src = (a == 0) ? g_xs : (a == 1) ? g_ys : (a == 2) ? g_w : g_rden;
                ((float4*)&shg[bl][a][0])[e4] =
                    *(const float4*)&(src[(bs+bl)*FP + gb + e4*4]);
            }
        }
        __syncthreads();
        #pragma unroll 1
        for (int bl = 0; bl < 8; bl++){
            float xf[4], yf[4];
            *(float4*)&xf[0] = ((float4*)&shf[bl][0][0])[ty];
            *(float4*)&yf[0] = ((float4*)&shf[bl][1][0])[ty];
            u64t xg2[4], yg2[4], wg2[4], rg2[4];
            {
                float4 q0 = ((float4*)&shg[bl][0][0])[tx*2], q1 = ((float4*)&shg[bl][0][0])[tx*2+1];
                xg2[0]=pk(q0.x,q0.y); xg2[1]=pk(q0.z,q0.w); xg2[2]=pk(q1.x,q1.y); xg2[3]=pk(q1.z,q1.w);
                q0 = ((float4*)&shg[bl][1][0])[tx*2]; q1 = ((float4*)&shg[bl][1][0])[tx*2+1];
                yg2[0]=pk(q0.x,q0.y); yg2[1]=pk(q0.z,q0.w); yg2[2]=pk(q1.x,q1.y); yg2[3]=pk(q1.z,q1.w);
                q0 = ((float4*)&shg[bl][2][0])[tx*2]; q1 = ((float4*)&shg[bl][2][0])[tx*2+1];
                wg2[0]=pk(q0.x,q0.y); wg2[1]=pk(q0.z,q0.w); wg2[2]=pk(q1.x,q1.y); wg2[3]=pk(q1.z,q1.w);
                q0 = ((float4*)&shg[bl][3][0])[tx*2]; q1 = ((float4*)&shg[bl][3][0])[tx*2+1];
                rg2[0]=pk(q0.x,q0.y); rg2[1]=pk(q0.z,q0.w); rg2[2]=pk(q1.x,q1.y); rg2[3]=pk(q1.z,q1.w);
            }
            u64t r1f2[4] = {0ULL,0ULL,0ULL,0ULL};
            #pragma unroll
            for (int i = 0; i < 4; i++){
                u64t xf2 = pk(xf[i], xf[i]), yf2 = pk(yf[i], yf[i]);
                #pragma unroll
                for (int j2 = 0; j2 < 4; j2++){
                    float a0, a1;
                    upk(fma2(xg2[j2], yf2, mul2(yg2[j2], xf2)), a0, a1);
                    u64t t2 = pk(fsqrt_a(a0), fsqrt_a(a1));
                    accA[i][j2] = fma2(t2, rg2[j2], accA[i][j2]);
                    r1f2[i]     = fma2(t2, wg2[j2], r1f2[i]);
                }
            }
            #pragma unroll
            for (int i = 0; i < 4; i++){
                float a0, a1; upk(r1f2[i], a0, a1);
                float v = a0 + a1;
                v += __shfl_xor_sync(0xffffffffu, v, 1);
                v += __shfl_xor_sync(0xffffffffu, v, 2);
                v += __shfl_xor_sync(0xffffffffu, v, 4);
                if (tx == 0)
                    atomicAdd(&g_s1[(bs+bl)*FP + fb + ty*4 + i], v);
            }
        }
    }

    // exclusive tile ownership: plain store with adjbuf + 64*eye folded in
    #pragma unroll
    for (int i = 0; i < 4; i++){
        int f = fb + ty*4 + i;
        int gBase = gb + tx*8;
        float vals[8];
        #pragma unroll
        for (int j2 = 0; j2 < 4; j2++) upk(accA[i][j2], vals[2*j2], vals[2*j2+1]);
        if (f < F){
            #pragma unroll
            for (int j = 0; j < 8; j++){
                int g = gBase + j;
                if (g < F) vals[j] += adjbuf[f*F + g];
                if (g == f) vals[j] += 64.0f;
            }
        }
        *(float4*)&g_adj[f*FP + gBase]     = *(float4*)&vals[0];
        *(float4*)&g_adj[f*FP + gBase + 4] = *(float4*)&vals[4];
    }
}

// ---------------- block reduction helper ------------------------------------
__device__ __forceinline__ float block_sum(float v, float* sred){
    #pragma unroll
    for (int m = 16; m; m >>= 1) v += __shfl_xor_sync(0xffffffffu, v, m);
    int lane = threadIdx.x & 31, w = threadIdx.x >> 5;
    __syncthreads();
    if (lane == 0) sred[w] = v;
    __syncthreads();
    if (w == 0){
        v = (lane < (int)(blockDim.x >> 5)) ? sred[lane] : 0.f;
        #pragma unroll
        for (int m = 16; m; m >>= 1) v += __shfl_xor_sync(0xffffffffu, v, m);
    }
    return v;
}

// ---------------- k_stats1: one-pass sum + sumsq of s1 ----------------------
__global__ void k_stats1(){
    __shared__ float sred[32];
    int idx = blockIdx.x * 1024 + threadIdx.x;       // exactly BB*FP
    float v = g_s1[idx];                              // pads are 0
    float s = block_sum(v, sred);
    if (threadIdx.x == 0) atomicAdd(&g_acc[0], s);
    float q = block_sum(v*v, sred);
    if (threadIdx.x == 0) atomicAdd(&g_acc[1], q);
}

// ---------------- k_hn1: BN1 + softsign, transposed [g][n] ------------------
__global__ void k_hn1(const float* __restrict__ W1, const float* __restrict__ g1,
                      const float* __restrict__ be1){
    int idx = blockIdx.x * 256 + threadIdx.x;
    if (idx >= FP*128) return;
    int g = idx >> 7, n = idx & 127;
    int b = n >> 1, c = n & 1;
    float out = 0.f;
    if (g < F){
        float ms = g_acc[0] * (1.f/NBF);
        float vs = g_acc[1] * (1.f/NBF) - ms*ms;
        float w  = W1[c];
        float A  = g1[c] * w * rsqrtf(w*w*vs + EPS);
        float h  = fmaf(A, g_s1[b*FP+g] - ms, be1[c]);
        out = h * frcp_a(1.f + fabsf(h));
    }
    g_hn[idx] = out;
}

// ---------------- k_gemm: z[f,n] = sum_g adj[f,g]*hn[g,n] -------------------
#define GK 96
#define GT 32
__global__ void __launch_bounds__(256) k_gemm(){
    __shared__ float sa[64][GT+1];
    __shared__ float sb[GT][128];
    int fb = blockIdx.x * 64;
    int g0base = blockIdx.y * GK;
    int tid = threadIdx.x, tx = tid & 15, ty = tid >> 4;
    u64t acc2[4][4];
    #pragma unroll
    for (int i = 0; i < 4; i++)
        #pragma unroll
        for (int j = 0; j < 4; j++) acc2[i][j] = 0ULL;
    for (int kc = 0; kc < GK; kc += GT){
        int g0 = g0base + kc;
        __syncthreads();
        for (int i = tid; i < 64*GT; i += 256){
            int r = i >> 5, c = i & 31;
            sa[r][c] = g_adj[(fb+r)*FP + g0 + c];
        }
        for (int i = tid; i < GT*32; i += 256){
            int r = i >> 5, c = i & 31;
            ((float4*)&sb[r][0])[c] = ((const float4*)(g_hn + (size_t)(g0+r)*128))[c];
        }
        __syncthreads();
        #pragma unroll
        for (int k = 0; k < GT; k++){
            u64t bv[4];
            {
                float4 q0 = ((float4*)&sb[k][0])[tx*2], q1 = ((float4*)&sb[k][0])[tx*2+1];
                bv[0]=pk(q0.x,q0.y); bv[1]=pk(q0.z,q0.w); bv[2]=pk(q1.x,q1.y); bv[3]=pk(q1.z,q1.w);
            }
            #pragma unroll
            for (int i = 0; i < 4; i++){
                float a = sa[ty*4+i][k];
                u64t a2 = pk(a, a);
                #pragma unroll
                for (int j = 0; j < 4; j++) acc2[i][j] = fma2(a2, bv[j], acc2[i][j]);
            }
        }
    }
    #pragma unroll
    for (int i = 0; i < 4; i++){
        float vals[8];
        #pragma unroll
        for (int j = 0; j < 4; j++) upk(acc2[i][j], vals[2*j], vals[2*j+1]);
        #pragma unroll
        for (int j = 0; j < 8; j++)
            atomicAdd(&g_z[(fb+ty*4+i)*128 + tx*8+j], vals[j]);
    }
}

// ---------------- k_stats2: one-pass BN2 sums --------------------------------
__global__ void k_stats2(const float* __restrict__ W2, const float* __restrict__ b2){
    __shared__ float sred[32];
    int idx = blockIdx.x * 1024 + threadIdx.x;
    float v0 = 0.f, v1 = 0.f;
    if (idx < BB*F){
        int f = idx >> 6, b = idx & 63;
        float z0 = g_z[f*128 + 2*b], z1 = g_z[f*128 + 2*b + 1];
        v0 = fmaf(W2[0], z0, fmaf(W2[1], z1, b2[0]));
        v1 = fmaf(W2[2], z0, fmaf(W2[3], z1, b2[1]));
    }
    float s;
    s = block_sum(v0,    sred); if (threadIdx.x == 0) atomicAdd(&g_acc[2], s);
    s = block_sum(v1,    sred); if (threadIdx.x == 0) atomicAdd(&g_acc[3], s);
    s = block_sum(v0*v0, sred); if (threadIdx.x == 0) atomicAdd(&g_acc[4], s);
    s = block_sum(v1*v1, sred); if (threadIdx.x == 0) atomicAdd(&g_acc[5], s);
}

// ---------------- k_final: BN2 + softsign + classifier ----------------------
__global__ void k_final(const float* __restrict__ W2, const float* __restrict__ b2,
                        const float* __restrict__ g2, const float* __restrict__ be2,
                        const float* __restrict__ Wc, const float* __restrict__ bc,
                        float* __restrict__ out){
    __shared__ float red[256];
    int b = blockIdx.x, tid = threadIdx.x;
    float m0 = g_acc[2] * (1.f/NBF), m1 = g_acc[3] * (1.f/NBF);
    float A0 = g2[0] * rsqrtf(g_acc[4]*(1.f/NBF) - m0*m0 + EPS);
    float A1 = g2[1] * rsqrtf(g_acc[5]*(1.f/NBF) - m1*m1 + EPS);
    float w00 = W2[0], w01 = W2[1], w10 = W2[2], w11 = W2[3];
    float bb0 = b2[0], bb1 = b2[1], e0 = be2[0], e1 = be2[1];
    float acc[NC] = {};
    for (int f = tid; f < F; f += 256){
        float z0 = g_z[f*128 + 2*b], z1 = g_z[f*128 + 2*b + 1];
        float h0 = fmaf(w00, z0, fmaf(w01, z1, bb0));
        h0 = fmaf(A0, h0 - m0, e0);
        h0 = h0 * frcp_a(1.f + fabsf(h0));
        float h1 = fmaf(w10, z0, fmaf(w11, z1, bb1));
        h1 = fmaf(A1, h1 - m1, e1);
        h1 = h1 * frcp_a(1.f + fabsf(h1));
        #pragma unroll
        for (int k = 0; k < NC; k++)
            acc[k] += fmaf(h0, Wc[k*(2*F) + f], h1 * Wc[k*(2*F) + F + f]);
    }
    for (int k = 0; k < NC; k++){
        __syncthreads();
        red[tid] = acc[k];
        __syncthreads();
        for (int s = 128; s; s >>= 1){ if (tid < s) red[tid] += red[tid+s]; __syncthreads(); }
        if (tid == 0) out[b*NC + k] = red[0] + bc[k];
    }
}

// ---------------- launch -----------------------------------------------------
extern "C" void kernel_launch(void* const* d_in, const int* in_sizes, int n_in,
                              void* d_out, int out_size){
    const float* x    = (const float*)d_in[0];
    const float* nb   = (const float*)d_in[1];
    const float* adjb = (const float*)d_in[2];
    const float* W1   = (const float*)d_in[3];
    const float* W2   = (const float*)d_in[5];
    const float* b2   = (const float*)d_in[6];
    const float* g1   = (const float*)d_in[7];
    const float* be1  = (const float*)d_in[8];
    const float* g2   = (const float*)d_in[9];
    const float* be2  = (const float*)d_in[10];
    const float* Wc   = (const float*)d_in[11];
    const float* bc   = (const float*)d_in[12];
    float* out = (float*)d_out;

    k_init<<<(FP*128)/256, 256>>>(x, nb);
    k_den<<<dim3(24, 12), 256>>>();
    k_rw<<<(BB*FP)/256, 256>>>();
    k_main<<<dim3(12, 24), 256>>>(adjb);
    k_stats1<<<(BB*FP)/1024, 1024>>>();
    k_hn1<<<(FP*128)/256, 256>>>(W1, g1, be1);
    k_gemm<<<dim3(24, FP/GK), 256>>>();
    k_stats2<<<(BB*F + 1023)/1024, 1024>>>(W2, b2);
    k_final<<<BB, 256>>>(W2, b2, g2, be2, Wc, bc, out);
}

// round 6
// speedup vs baseline: 1.0643x; 1.0603x over previous
#include <cuda_runtime.h>
#include <math.h>

#define F    1433
#define FP   1536
#define BB   64
#define KNB  8
#define NC   7
#define NT   24
#define NBF  91712.0f      // BB * F
#define EPS  1e-5f

__device__ float g_xs  [BB*FP];
__device__ float g_ys  [BB*FP];
__device__ float g_den [BB*FP];
__device__ float g_rden[BB*FP];
__device__ float g_s1  [BB*FP];
__device__ float g_adjA[FP*FP];
__device__ float g_adjB[FP*FP];
__device__ float g_hn  [FP*128];
__device__ float g_z   [FP*128];
__device__ float g_acc [8];

typedef unsigned long long u64t;

__device__ __forceinline__ float fsqrt_a(float x){ float r; asm("sqrt.approx.f32 %0,%1;" : "=f"(r) : "f"(x)); return r; }
__device__ __forceinline__ float frcp_a (float x){ float r; asm("rcp.approx.f32 %0,%1;"  : "=f"(r) : "f"(x)); return r; }
__device__ __forceinline__ u64t pk(float a, float b){ u64t r; asm("mov.b64 %0,{%1,%2};" : "=l"(r) : "f"(a), "f"(b)); return r; }
__device__ __forceinline__ void upk(u64t v, float &a, float &b){ asm("mov.b64 {%0,%1},%2;" : "=f"(a), "=f"(b) : "l"(v)); }
__device__ __forceinline__ u64t fma2(u64t a, u64t b, u64t c){ u64t r; asm("fma.rn.f32x2 %0,%1,%2,%3;" : "=l"(r) : "l"(a), "l"(b), "l"(c)); return r; }
__device__ __forceinline__ u64t mul2(u64t a, u64t b){ u64t r; asm("mul.rn.f32x2 %0,%1,%2;" : "=l"(r) : "l"(a), "l"(b)); return r; }
__device__ __forceinline__ u64t add2(u64t a, u64t b){ u64t r; asm("add.rn.f32x2 %0,%1,%2;" : "=l"(r) : "l"(a), "l"(b)); return r; }

__device__ __forceinline__ void pair_decode(int p, int &I, int &J){
    int i = 0, rem = p;
    while (rem >= NT - i){ rem -= NT - i; i++; }
    I = i; J = i + rem;
}

// ---------------- k_init ----------------
__global__ void k_init(const float* __restrict__ x, const float* __restrict__ nb){
    int idx = blockIdx.x * 256 + threadIdx.x;        // covers FP*128
    if (idx < 8) g_acc[idx] = 0.f;
    g_z[idx] = 0.f;
    if (idx < BB*FP){
        int b = idx / FP, g = idx - b*FP;
        float xv = 0.f, yv = 0.f;
        if (g < F){
            xv = x[b*F + g];
            const float* p = nb + (size_t)b*KNB*F + g;
            #pragma unroll
            for (int k = 0; k < KNB; k++) yv += p[k*F];
        }
        g_xs[idx] = xv; g_ys[idx] = yv; g_den[idx] = 0.f;
    }
}

// ---------------- k_den: symmetric pairs, batch-split x2 (600 blocks) -------
__global__ void __launch_bounds__(256,4) k_den(){
    __shared__ float shf[8][2][64];
    __shared__ float shg[8][2][64];
    __shared__ u64t  cbuf[8][8][32];
    int pair = blockIdx.x >> 1, bh = blockIdx.x & 1;
    int I, J; pair_decode(pair, I, J);
    bool off = (I != J);
    int fb = I*64, gb = J*64;
    int tid = threadIdx.x, tx = tid & 7, ty = tid >> 3, w = tid >> 5;
    int bs0 = bh * 32;

    for (int st = 0; st < 4; st++){
        int bs = bs0 + st*8;
        __syncthreads();
        for (int v = tid; v < 512; v += 256){
            int bl = v >> 6, e = v & 63, base = (bs+bl)*FP;
            shf[bl][0][e] = g_xs[base+fb+e]; shf[bl][1][e] = g_ys[base+fb+e];
            shg[bl][0][e] = g_xs[base+gb+e]; shg[bl][1][e] = g_ys[base+gb+e];
        }
        __syncthreads();
        #pragma unroll 1
        for (int bl = 0; bl < 8; bl++){
            u64t xg2[4], yg2[4];
            {
                float4 q0 = ((float4*)&shg[bl][0][0])[tx*2], q1 = ((float4*)&shg[bl][0][0])[tx*2+1];
                xg2[0]=pk(q0.x,q0.y); xg2[1]=pk(q0.z,q0.w); xg2[2]=pk(q1.x,q1.y); xg2[3]=pk(q1.z,q1.w);
                q0 = ((float4*)&shg[bl][1][0])[tx*2]; q1 = ((float4*)&shg[bl][1][0])[tx*2+1];
                yg2[0]=pk(q0.x,q0.y); yg2[1]=pk(q0.z,q0.w); yg2[2]=pk(q1.x,q1.y); yg2[3]=pk(q1.z,q1.w);
            }
            u64t cs2[4] = {0ULL,0ULL,0ULL,0ULL};
            #pragma unroll
            for (int i = 0; i < 2; i++){
                float xf = shf[bl][0][ty*2+i], yf = shf[bl][1][ty*2+i];
                u64t xf2 = pk(xf, xf), yf2 = pk(yf, yf);
                u64t rs = 0ULL;
                #pragma unroll
                for (int j2 = 0; j2 < 4; j2++){
                    float a0, a1;
                    upk(fma2(xg2[j2], yf2, mul2(yg2[j2], xf2)), a0, a1);
                    u64t t2 = pk(fsqrt_a(a0), fsqrt_a(a1));
                    cs2[j2] = add2(cs2[j2], t2);
                    rs      = add2(rs, t2);
                }
                if (off){
                    float p0, p1; upk(rs, p0, p1);
                    float v = p0 + p1;
                    v += __shfl_xor_sync(0xffffffffu, v, 1);
                    v += __shfl_xor_sync(0xffffffffu, v, 2);
                    v += __shfl_xor_sync(0xffffffffu, v, 4);
                    if (tx == 0) atomicAdd(&g_den[(bs+bl)*FP + fb + ty*2 + i], v);
                }
            }
            #pragma unroll
            for (int j2 = 0; j2 < 4; j2++){
                cs2[j2] = add2(cs2[j2], __shfl_xor_sync(0xffffffffu, cs2[j2], 8));
                cs2[j2] = add2(cs2[j2], __shfl_xor_sync(0xffffffffu, cs2[j2], 16));
            }
            if ((tid & 31) < 8){
                #pragma unroll
                for (int j2 = 0; j2 < 4; j2++) cbuf[bl][w][tx*4+j2] = cs2[j2];
            }
        }
        __syncthreads();
        for (int o = tid; o < 512; o += 256){
            int bl = o >> 6, g = o & 63;
            float s = 0.f;
            #pragma unroll
            for (int w2 = 0; w2 < 8; w2++) s += ((float*)&cbuf[bl][w2][0])[g];
            atomicAdd(&g_den[(bs+bl)*FP + gb + g], s);
        }
    }
}

// ---------------- k_rw ----------------
__global__ void k_rw(){
    int idx = blockIdx.x * 256 + threadIdx.x;
    if (idx >= BB*FP) return;
    int g = idx % FP;
    float d = g_den[idx];
    float r = (g < F && d > 0.f) ? frcp_a(d) : 0.f;
    g_rden[idx] = r;
    g_s1[idx]   = (g < F) ? g_xs[idx] : 0.f;
}

// ---------------- k_main: symmetric adj pair + s1, batch-split x2 -----------
__global__ void __launch_bounds__(256,2) k_main(const float* __restrict__ adjbuf){
    __shared__ float4 shfq[8][64];      // {xf, yf, wf=xf*rf, rf}
    __shared__ float  shg[8][3][64];    // {xg, yg, rg}
    __shared__ u64t   cbuf[8][8][32];
    int pair = blockIdx.x >> 1, bh = blockIdx.x & 1;
    int I, J; pair_decode(pair, I, J);
    bool off = (I != J);
    int fb = I*64, gb = J*64;
    int tid = threadIdx.x, tx = tid & 7, ty = tid >> 3, w = tid >> 5;
    int bs0 = bh * 32;

    u64t accA[2][4], accB[2][4];
    #pragma unroll
    for (int i = 0; i < 2; i++)
        #pragma unroll
        for (int j = 0; j < 4; j++){ accA[i][j] = 0ULL; accB[i][j] = 0ULL; }

    for (int st = 0; st < 4; st++){
        int bs = bs0 + st*8;
        __syncthreads();
        for (int v = tid; v < 512; v += 256){
            int bl = v >> 6, e = v & 63, base = (bs+bl)*FP;
            float xf = g_xs[base+fb+e], yf = g_ys[base+fb+e], rf = g_rden[base+fb+e];
            shfq[bl][e] = make_float4(xf, yf, xf*rf, rf);
            shg[bl][0][e] = g_xs[base+gb+e];
            shg[bl][1][e] = g_ys[base+gb+e];
            shg[bl][2][e] = g_rden[base+gb+e];
        }
        __syncthreads();
        #pragma unroll 1
        for (int bl = 0; bl < 8; bl++){
            u64t xg2[4], yg2[4], rg2[4];
            {
                float4 q0 = ((float4*)&shg[bl][0][0])[tx*2], q1 = ((float4*)&shg[bl][0][0])[tx*2+1];
                xg2[0]=pk(q0.x,q0.y); xg2[1]=pk(q0.z,q0.w); xg2[2]=pk(q1.x,q1.y); xg2[3]=pk(q1.z,q1.w);
                q0 = ((float4*)&shg[bl][1][0])[tx*2]; q1 = ((float4*)&shg[bl][1][0])[tx*2+1];
                yg2[0]=pk(q0.x,q0.y); yg2[1]=pk(q0.z,q0.w); yg2[2]=pk(q1.x,q1.y); yg2[3]=pk(q1.z,q1.w);
                q0 = ((float4*)&shg[bl][2][0])[tx*2]; q1 = ((float4*)&shg[bl][2][0])[tx*2+1];
                rg2[0]=pk(q0.x,q0.y); rg2[1]=pk(q0.z,q0.w); rg2[2]=pk(q1.x,q1.y); rg2[3]=pk(q1.z,q1.w);
            }
            u64t c1[4] = {0ULL,0ULL,0ULL,0ULL};
            #pragma unroll
            for (int i = 0; i < 2; i++){
                float4 fv = shfq[bl][ty*2+i];
                u64t xf2 = pk(fv.x, fv.x), yf2 = pk(fv.y, fv.y);
                u64t wf2 = pk(fv.z, fv.z), rf2 = pk(fv.w, fv.w);
                u64t r1 = 0ULL;
                #pragma unroll
                for (int j2 = 0; j2 < 4; j2++){
                    float a0, a1;
                    upk(fma2(xg2[j2], yf2, mul2(yg2[j2], xf2)), a0, a1);
                    u64t t2 = pk(fsqrt_a(a0), fsqrt_a(a1));
                    u64t dA = mul2(t2, rg2[j2]);
                    accA[i][j2] = add2(accA[i][j2], dA);
                    r1          = fma2(dA, xg2[j2], r1);
                    if (off){
                        accB[i][j2] = fma2(t2, rf2, accB[i][j2]);
                        c1[j2]      = fma2(t2, wf2, c1[j2]);
                    }
                }
                float p0, p1; upk(r1, p0, p1);
                float v = p0 + p1;
                v += __shfl_xor_sync(0xffffffffu, v, 1);
                v += __shfl_xor_sync(0xffffffffu, v, 2);
                v += __shfl_xor_sync(0xffffffffu, v, 4);
                if (tx == 0) atomicAdd(&g_s1[(bs+bl)*FP + fb + ty*2 + i], v);
            }
            if (off){
                #pragma unroll
                for (int j2 = 0; j2 < 4; j2++){
                    c1[j2] = add2(c1[j2], __shfl_xor_sync(0xffffffffu, c1[j2], 8));
                    c1[j2] = add2(c1[j2], __shfl_xor_sync(0xffffffffu, c1[j2], 16));
                }
                if ((tid & 31) < 8){
                    #pragma unroll
                    for (int j2 = 0; j2 < 4; j2++) cbuf[bl][w][tx*4+j2] = c1[j2];
                }
            }
        }
        __syncthreads();
        if (off){
            for (int o = tid; o < 512; o += 256){
                int bl = o >> 6, g = o & 63;
                float s = 0.f;
                #pragma unroll
                for (int w2 = 0; w2 < 8; w2++) s += ((float*)&cbuf[bl][w2][0])[g];
                atomicAdd(&g_s1[(bs+bl)*FP + gb + g], s);
            }
        }
    }

    // epilogue: exclusive tiles per (pair, bhalf) -> plain stores
    float* dst = bh ? g_adjB : g_adjA;
    #pragma unroll
    for (int i = 0; i < 2; i++){
        int f = fb + ty*2 + i;
        int gB = gb + tx*8;
        float vals[8];
        #pragma unroll
        for (int j2 = 0; j2 < 4; j2++) upk(accA[i][j2], vals[2*j2], vals[2*j2+1]);
        if (bh == 0 && f < F){
            #pragma unroll
            for (int j = 0; j < 8; j++){
                int g = gB + j;
                if (g < F) vals[j] += adjbuf[f*F + g];
                if (g == f) vals[j] += 64.0f;
            }
        }
        *(float4*)&dst[f*FP + gB]     = *(float4*)&vals[0];
        *(float4*)&dst[f*FP + gB + 4] = *(float4*)&vals[4];
    }
    if (off){
        #pragma unroll
        for (int i = 0; i < 2; i++){
            int f = fb + ty*2 + i;
            #pragma unroll
            for (int j2 = 0; j2 < 4; j2++){
                float v0, v1; upk(accB[i][j2], v0, v1);
                int g0 = gb + tx*8 + 2*j2, g1 = g0 + 1;
                if (bh == 0 && f < F){
                    if (g0 < F) v0 += adjbuf[g0*F + f];
                    if (g1 < F) v1 += adjbuf[g1*F + f];
                }
                dst[g0*FP + f] = v0;
                dst[g1*FP + f] = v1;
            }
        }
    }
}

// ---------------- block reduction helper ------------------------------------
__device__ __forceinline__ float block_sum(float v, float* sred){
    #pragma unroll
    for (int m = 16; m; m >>= 1) v += __shfl_xor_sync(0xffffffffu, v, m);
    int lane = threadIdx.x & 31, w = threadIdx.x >> 5;
    __syncthreads();
    if (lane == 0) sred[w] = v;
    __syncthreads();
    if (w == 0){
        v = (lane < (int)(blockDim.x >> 5)) ? sred[lane] : 0.f;
        #pragma unroll
        for (int m = 16; m; m >>= 1) v += __shfl_xor_sync(0xffffffffu, v, m);
    }
    return v;
}

// ---------------- k_stats1 ----------------
__global__ void k_stats1(){
    __shared__ float sred[32];
    int idx = blockIdx.x * 1024 + threadIdx.x;       // exactly BB*FP
    float v = g_s1[idx];
    float s = block_sum(v, sred);
    if (threadIdx.x == 0) atomicAdd(&g_acc[0], s);
    float q = block_sum(v*v, sred);
    if (threadIdx.x == 0) atomicAdd(&g_acc[1], q);
}

// ---------------- k_hn1 ----------------
__global__ void k_hn1(const float* __restrict__ W1, const float* __restrict__ g1,
                      const float* __restrict__ be1){
    int idx = blockIdx.x * 256 + threadIdx.x;
    if (idx >= FP*128) return;
    int g = idx >> 7, n = idx & 127;
    int b = n >> 1, c = n & 1;
    float out = 0.f;
    if (g < F){
        float ms = g_acc[0] * (1.f/NBF);
        float vs = g_acc[1] * (1.f/NBF) - ms*ms;
        float wv = W1[c];
        float A  = g1[c] * wv * rsqrtf(wv*wv*vs + EPS);
        float h  = fmaf(A, g_s1[b*FP+g] - ms, be1[c]);
        out = h * frcp_a(1.f + fabsf(h));
    }
    g_hn[idx] = out;
}

// ---------------- k_gemm: z = (adjA + adjB) * hn -----------------------------
#define GK 96
#define GT 32
__global__ void __launch_bounds__(256) k_gemm(){
    __shared__ float sa[64][GT+1];
    __shared__ float sb[GT][128];
    int fb = blockIdx.x * 64;
    int g0base = blockIdx.y * GK;
    int tid = threadIdx.x, tx = tid & 15, ty = tid >> 4;
    u64t acc2[4][4];
    #pragma unroll
    for (int i = 0; i < 4; i++)
        #pragma unroll
        for (int j = 0; j < 4; j++) acc2[i][j] = 0ULL;
    for (int kc = 0; kc < GK; kc += GT){
        int g0 = g0base + kc;
        __syncthreads();
        for (int i = tid; i < 64*GT; i += 256){
            int r = i >> 5, c = i & 31;
            int idx = (fb+r)*FP + g0 + c;
            sa[r][c] = g_adjA[idx] + g_adjB[idx];
        }
        for (int i = tid; i < GT*32; i += 256){
            int r = i >> 5, c = i & 31;
            ((float4*)&sb[r][0])[c] = ((const float4*)(g_hn + (size_t)(g0+r)*128))[c];
        }
        __syncthreads();
        #pragma unroll
        for (int k = 0; k < GT; k++){
            u64t bv[4];
            {
                float4 q0 = ((float4*)&sb[k][0])[tx*2], q1 = ((float4*)&sb[k][0])[tx*2+1];
                bv[0]=pk(q0.x,q0.y); bv[1]=pk(q0.z,q0.w); bv[2]=pk(q1.x,q1.y); bv[3]=pk(q1.z,q1.w);
            }
            #pragma unroll
            for (int i = 0; i < 4; i++){
                float a = sa[ty*4+i][k];
                u64t a2 = pk(a, a);
                #pragma unroll
                for (int j = 0; j < 4; j++) acc2[i][j] = fma2(a2, bv[j], acc2[i][j]);
            }
        }
    }
    #pragma unroll
    for (int i = 0; i < 4; i++){
        float vals[8];
        #pragma unroll
        for (int j = 0; j < 4; j++) upk(acc2[i][j], vals[2*j], vals[2*j+1]);
        #pragma unroll
        for (int j = 0; j < 8; j++)
            atomicAdd(&g_z[(fb+ty*4+i)*128 + tx*8+j], vals[j]);
    }
}

// ---------------- k_stats2 ----------------
__global__ void k_stats2(const float* __restrict__ W2, const float* __restrict__ b2){
    __shared__ float sred[32];
    int idx = blockIdx.x * 1024 + threadIdx.x;
    float v0 = 0.f, v1 = 0.f;
    if (idx < BB*F){
        int f = idx >> 6, b = idx & 63;
        float z0 = g_z[f*128 + 2*b], z1 = g_z[f*128 + 2*b + 1];
        v0 = fmaf(W2[0], z0, fmaf(W2[1], z1, b2[0]));
        v1 = fmaf(W2[2], z0, fmaf(W2[3], z1, b2[1]));
    }
    float s;
    s = block_sum(v0,    sred); if (threadIdx.x == 0) atomicAdd(&g_acc[2], s);
    s = block_sum(v1,    sred); if (threadIdx.x == 0) atomicAdd(&g_acc[3], s);
    s = block_sum(v0*v0, sred); if (threadIdx.x == 0) atomicAdd(&g_acc[4], s);
    s = block_sum(v1*v1, sred); if (threadIdx.x == 0) atomicAdd(&g_acc[5], s);
}

// ---------------- k_final ----------------
__global__ void k_final(const float* __restrict__ W2, const float* __restrict__ b2,
                        const float* __restrict__ g2, const float* __restrict__ be2,
                        const float* __restrict__ Wc, const float* __restrict__ bc,
                        float* __restrict__ out){
    __shared__ float red[256];
    int b = blockIdx.x, tid = threadIdx.x;
    float m0 = g_acc[2] * (1.f/NBF), m1 = g_acc[3] * (1.f/NBF);
    float A0 = g2[0] * rsqrtf(g_acc[4]*(1.f/NBF) - m0*m0 + EPS);
    float A1 = g2[1] * rsqrtf(g_acc[5]*(1.f/NBF) - m1*m1 + EPS);
    float w00 = W2[0], w01 = W2[1], w10 = W2[2], w11 = W2[3];
    float bb0 = b2[0], bb1 = b2[1], e0 = be2[0], e1 = be2[1];
    float acc[NC] = {};
    for (int f = tid; f < F; f += 256){
        float z0 = g_z[f*128 + 2*b], z1 = g_z[f*128 + 2*b + 1];
        float h0 = fmaf(w00, z0, fmaf(w01, z1, bb0));
        h0 = fmaf(A0, h0 - m0, e0);
        h0 = h0 * frcp_a(1.f + fabsf(h0));
        float h1 = fmaf(w10, z0, fmaf(w11, z1, bb1));
        h1 = fmaf(A1, h1 - m1, e1);
        h1 = h1 * frcp_a(1.f + fabsf(h1));
        #pragma unroll
        for (int k = 0; k < NC; k++)
            acc[k] += fmaf(h0, Wc[k*(2*F) + f], h1 * Wc[k*(2*F) + F + f]);
    }
    for (int k = 0; k < NC; k++){
        __syncthreads();
        red[tid] = acc[k];
        __syncthreads();
        for (int s = 128; s; s >>= 1){ if (tid < s) red[tid] += red[tid+s]; __syncthreads(); }
        if (tid == 0) out[b*NC + k] = red[0] + bc[k];
    }
}

// ---------------- launch ------------------------------------------------------
extern "C" void kernel_launch(void* const* d_in, const int* in_sizes, int n_in,
                              void* d_out, int out_size){
    const float* x    = (const float*)d_in[0];
    const float* nb   = (const float*)d_in[1];
    const float* adjb = (const float*)d_in[2];
    const float* W1   = (const float*)d_in[3];
    const float* W2   = (const float*)d_in[5];
    const float* b2   = (const float*)d_in[6];
    const float* g1   = (const float*)d_in[7];
    const float* be1  = (const float*)d_in[8];
    const float* g2   = (const float*)d_in[9];
    const float* be2  = (const float*)d_in[10];
    const float* Wc   = (const float*)d_in[11];
    const float* bc   = (const float*)d_in[12];
    float* out = (float*)d_out;

    k_init<<<(FP*128)/256, 256>>>(x, nb);
    k_den<<<600, 256>>>();
    k_rw<<<(BB*FP)/256, 256>>>();
    k_main<<<600, 256>>>(adjb);
    k_stats1<<<(BB*FP)/1024, 1024>>>();
    k_hn1<<<(FP*128)/256, 256>>>(W1, g1, be1);
    k_gemm<<<dim3(24, FP/GK), 256>>>();
    k_stats2<<<(BB*F + 1023)/1024, 1024>>>(W2, b2);
    k_final<<<BB, 256>>>(W2, b2, g2, be2, Wc, bc, out);
}